// round 9
// baseline (speedup 1.0000x reference)
#include <cuda_runtime.h>

#define BATCH 1024
#define TT    512
#define DIN   32
#define H     64
#define NROWS 256
#define BT    (BATCH * TT)
#define HP    72          // padded h row stride: banks 8b..8b+7 per batch

typedef unsigned long long ull;

__device__ float g_xg0[(size_t)BT * NROWS];
__device__ float g_xg1[(size_t)BT * NROWS];
__device__ float g_h1 [(size_t)BT * H];

// ---------------------------------------------------------------------------
__device__ __forceinline__ void ffma2(ull& acc, ull w, ull v) {
    asm("fma.rn.f32x2 %0, %1, %2, %0;" : "+l"(acc) : "l"(w), "l"(v));
}
__device__ __forceinline__ float f2sum(ull a) {
    return __uint_as_float((unsigned)(a & 0xffffffffull)) +
           __uint_as_float((unsigned)(a >> 32));
}
__device__ __forceinline__ float tanh_f(float x) {
    return 1.0f - __fdividef(2.0f, __expf(2.0f * x) + 1.0f);
}
__device__ __forceinline__ float sigm(float x) {
    return __fdividef(1.0f, 1.0f + __expf(-x));
}
__device__ __forceinline__ int slot_row(int s) { return (s & 3) * H + (s >> 2); }

// ---------------------------------------------------------------------------
// GEMM K=32 (layer-0 input part): 128 thr, 2 slots/thread.
// ---------------------------------------------------------------------------
__global__ void __launch_bounds__(128)
gemm_xg32(const float* __restrict__ X, const float* __restrict__ Wih,
          const float* __restrict__ bih, const float* __restrict__ bhh,
          float* __restrict__ out)
{
    constexpr int K = 32, ROWS = 128;
    __shared__ __align__(16) float xs[ROWS * K];

    const int tid = threadIdx.x;
    const int s0 = tid, s1 = tid + 128;
    const int r0 = slot_row(s0), r1 = slot_row(s1);

    ull w0[K / 2], w1[K / 2];
    #pragma unroll
    for (int i = 0; i < K / 2; i++) {
        w0[i] = reinterpret_cast<const ull*>(Wih + r0 * K)[i];
        w1[i] = reinterpret_cast<const ull*>(Wih + r1 * K)[i];
    }
    const float bias0 = bih[r0] + bhh[r0];
    const float bias1 = bih[r1] + bhh[r1];

    const size_t rowBase = (size_t)blockIdx.x * ROWS;
    const float4* src = reinterpret_cast<const float4*>(X + rowBase * K);
    float4* dst = reinterpret_cast<float4*>(xs);
    #pragma unroll
    for (int i = tid; i < ROWS * K / 4; i += 128) dst[i] = src[i];
    __syncthreads();

    #pragma unroll 4
    for (int row = 0; row < ROWS; row++) {
        const ulonglong2* xr = reinterpret_cast<const ulonglong2*>(xs + row * K);
        ull a0 = 0ull, a1 = 0ull;
        #pragma unroll
        for (int kk = 0; kk < K / 4; kk++) {
            ulonglong2 xv = xr[kk];
            ffma2(a0, w0[2 * kk], xv.x);  ffma2(a0, w0[2 * kk + 1], xv.y);
            ffma2(a1, w1[2 * kk], xv.x);  ffma2(a1, w1[2 * kk + 1], xv.y);
        }
        float* o = out + (rowBase + row) * NROWS;
        o[s0] = bias0 + f2sum(a0);
        o[s1] = bias1 + f2sum(a1);
    }
}

// ---------------------------------------------------------------------------
// GEMM K=64 (layer-1 input part), split-K halves, shfl_xor(16) combine.
// ---------------------------------------------------------------------------
__global__ void __launch_bounds__(256)
gemm_xg64(const float* __restrict__ X, const float* __restrict__ Wih,
          const float* __restrict__ bih, const float* __restrict__ bhh,
          float* __restrict__ out)
{
    constexpr int K = 64, ROWS = 128;
    __shared__ __align__(16) float xs[ROWS * K];

    const int tid  = threadIdx.x;
    const int lane = tid & 31;
    const int wrp  = tid >> 5;
    const int half = (lane >> 4) & 1;
    const int pid  = wrp * 16 + (lane & 15);
    const int s0 = pid, s1 = pid + 128;
    const int r0 = slot_row(s0), r1 = slot_row(s1);

    ull w0[16], w1[16];
    #pragma unroll
    for (int i = 0; i < 16; i++) {
        w0[i] = reinterpret_cast<const ull*>(Wih + r0 * K + half * 32)[i];
        w1[i] = reinterpret_cast<const ull*>(Wih + r1 * K + half * 32)[i];
    }
    const float bias  = half ? (bih[r1] + bhh[r1]) : (bih[r0] + bhh[r0]);
    const int myslot  = half ? s1 : s0;

    const size_t rowBase = (size_t)blockIdx.x * ROWS;
    const float4* src = reinterpret_cast<const float4*>(X + rowBase * K);
    float4* dst = reinterpret_cast<float4*>(xs);
    #pragma unroll
    for (int i = tid; i < ROWS * K / 4; i += 256) dst[i] = src[i];
    __syncthreads();

    #pragma unroll 4
    for (int row = 0; row < ROWS; row++) {
        const ulonglong2* xr =
            reinterpret_cast<const ulonglong2*>(xs + row * K + half * 32);
        ull a0 = 0ull, a1 = 0ull;
        #pragma unroll
        for (int kk = 0; kk < 8; kk++) {
            ulonglong2 xv = xr[kk];
            ffma2(a0, w0[2 * kk], xv.x);  ffma2(a0, w0[2 * kk + 1], xv.y);
            ffma2(a1, w1[2 * kk], xv.x);  ffma2(a1, w1[2 * kk + 1], xv.y);
        }
        float v0 = f2sum(a0), v1 = f2sum(a1);
        float send = half ? v0 : v1;
        float recv = __shfl_xor_sync(0xffffffffu, send, 16);
        float mine = (half ? v1 : v0) + recv;
        out[(rowBase + row) * NROWS + myslot] = bias + mine;
    }
}

// ---------------------------------------------------------------------------
// Recurrent kernel: 256 thr, NB=4, grid=256, 2 CTAs/SM (~110 regs).
// lane bits: gp = b0, jmid = b3:1, half = b4.  j = warp*8 + jmid.
// Thread holds 2 gate rows of j (gp=0: i,g ; gp=1: f,o) over K-half `half`
// (64 weight regs). Butterfly: xor16 sums K-halves (keep 2 batches of 4),
// xor1 swaps gate-pairs for the owned batch b_own = 2*half+gp. 6 SHFL total.
// Owner applies activations + cell update in place. One barrier per step.
// ---------------------------------------------------------------------------
template <bool FIRST>
__global__ void __launch_bounds__(256, 2)
lstm_rec(const float* __restrict__ xg,    // [BT][NROWS], bias folded in
         const float* __restrict__ Whh,   // [NROWS][H]
         float* __restrict__ h1out,
         const float* __restrict__ Wfc,
         const float* __restrict__ bfc,
         float* __restrict__ out)
{
    __shared__ __align__(16) float hs[2][4 * HP];

    const int tid  = threadIdx.x;
    const int lane = tid & 31;
    const int wrp  = tid >> 5;
    const int gp   = lane & 1;
    const int jmid = (lane >> 1) & 7;
    const int half = (lane >> 4) & 1;
    const int j    = wrp * 8 + jmid;
    const int b_own = 2 * half + gp;
    const int b0   = blockIdx.x * 4;

    const int rA = gp * H + j;          // i (gp=0) or f (gp=1)
    const int rB = (gp + 2) * H + j;    // g (gp=0) or o (gp=1)

    // half-K rows: 16 packed pairs each
    ull wA[16], wB[16];
    #pragma unroll
    for (int i = 0; i < 16; i++) {
        wA[i] = reinterpret_cast<const ull*>(Whh + rA * H + half * 32)[i];
        wB[i] = reinterpret_cast<const ull*>(Whh + rB * H + half * 32)[i];
    }

    const float* xgp = xg + ((size_t)(b0 + b_own) * TT) * NROWS + j * 4;
    float* h1p = FIRST ? (h1out + ((size_t)(b0 + b_own) * TT) * H + j) : nullptr;

    float c = 0.0f;
    for (int i = tid; i < 4 * HP; i += 256) hs[0][i] = 0.0f;

    float4 xg4 = *reinterpret_cast<const float4*>(xgp);
    __syncthreads();

    for (int t = 0; t < TT; t++) {
        const int cur = t & 1, nxt = cur ^ 1;

        float4 xg4n;
        if (t + 1 < TT)
            xg4n = *reinterpret_cast<const float4*>(xgp + (size_t)(t + 1) * NROWS);

        // half-dots: sA/sB[b] for the 2 rows x 4 batches
        float sA[4], sB[4];
        const float* hq = hs[cur] + half * 32;
        #pragma unroll
        for (int b = 0; b < 4; b++) {
            const ulonglong2* hb = reinterpret_cast<const ulonglong2*>(hq + b * HP);
            ull aA = 0ull, aB = 0ull;
            #pragma unroll
            for (int kk = 0; kk < 4; kk++) {
                ulonglong2 hv = hb[kk];
                ffma2(aA, wA[2 * kk],     hv.x);
                ffma2(aA, wA[2 * kk + 1], hv.y);
                ffma2(aB, wB[2 * kk],     hv.x);
                ffma2(aB, wB[2 * kk + 1], hv.y);
            }
            #pragma unroll
            for (int kk = 4; kk < 8; kk++) {
                ulonglong2 hv = hb[kk];
                ffma2(aA, wA[2 * kk],     hv.x);
                ffma2(aA, wA[2 * kk + 1], hv.y);
                ffma2(aB, wB[2 * kk],     hv.x);
                ffma2(aB, wB[2 * kk + 1], hv.y);
            }
            sA[b] = f2sum(aA);
            sB[b] = f2sum(aB);
        }

        // round 1: xor16 — combine K-halves, keep batches {2*half, 2*half+1}
        float tA[2], tB[2];
        #pragma unroll
        for (int p = 0; p < 2; p++) {
            float sndA = half ? sA[p] : sA[2 + p];
            float sndB = half ? sB[p] : sB[2 + p];
            float rcvA = __shfl_xor_sync(0xffffffffu, sndA, 16);
            float rcvB = __shfl_xor_sync(0xffffffffu, sndB, 16);
            tA[p] = (half ? sA[2 + p] : sA[p]) + rcvA;
            tB[p] = (half ? sB[2 + p] : sB[p]) + rcvB;
        }
        // round 2: xor1 — swap gate-pairs for owned batch (partner sends
        // its t[.][gp^1 of partner] == our p = gp)
        float sndA = gp ? tA[0] : tA[1];
        float sndB = gp ? tB[0] : tB[1];
        float rcvA = __shfl_xor_sync(0xffffffffu, sndA, 1);
        float rcvB = __shfl_xor_sync(0xffffffffu, sndB, 1);
        float mineA = gp ? tA[1] : tA[0];   // own rows, batch b_own
        float mineB = gp ? tB[1] : tB[0];

        float gi = (gp ? rcvA : mineA) + xg4.x;
        float gf = (gp ? mineA : rcvA) + xg4.y;
        float gg = (gp ? rcvB : mineB) + xg4.z;
        float go = (gp ? mineB : rcvB) + xg4.w;

        c = fmaf(sigm(gf), c, sigm(gi) * tanh_f(gg));
        float hh = sigm(go) * tanh_f(c);
        hs[nxt][b_own * HP + j] = hh;
        if (FIRST) h1p[(size_t)t * H] = hh;

        xg4 = xg4n;
        __syncthreads();
    }

    if (!FIRST && tid < 4) {
        float a = bfc[0];
        #pragma unroll
        for (int k = 0; k < H; k++) a = fmaf(hs[0][tid * HP + k], Wfc[k], a);
        out[b0 + tid] = a;
    }
}

// ---------------------------------------------------------------------------
extern "C" void kernel_launch(void* const* d_in, const int* in_sizes, int n_in,
                              void* d_out, int out_size)
{
    const float* x    = (const float*)d_in[0];
    const float* Wih0 = (const float*)d_in[1];
    const float* Whh0 = (const float*)d_in[2];
    const float* bih0 = (const float*)d_in[3];
    const float* bhh0 = (const float*)d_in[4];
    const float* Wih1 = (const float*)d_in[5];
    const float* Whh1 = (const float*)d_in[6];
    const float* bih1 = (const float*)d_in[7];
    const float* bhh1 = (const float*)d_in[8];
    const float* Wfc  = (const float*)d_in[9];
    const float* bfc  = (const float*)d_in[10];
    float* out = (float*)d_out;

    float *xg0, *xg1, *h1;
    cudaGetSymbolAddress((void**)&xg0, g_xg0);
    cudaGetSymbolAddress((void**)&xg1, g_xg1);
    cudaGetSymbolAddress((void**)&h1,  g_h1);

    gemm_xg32<<<BT / 128, 128>>>(x, Wih0, bih0, bhh0, xg0);
    lstm_rec<true><<<BATCH / 4, 256>>>(xg0, Whh0, h1, nullptr, nullptr, nullptr);
    gemm_xg64<<<BT / 128, 256>>>(h1, Wih1, bih1, bhh1, xg1);
    lstm_rec<false><<<BATCH / 4, 256>>>(xg1, Whh1, nullptr, Wfc, bfc, out);
}